// round 4
// baseline (speedup 1.0000x reference)
#include <cuda_runtime.h>

#define NB 32
#define NC 64
#define NT 256
#define NV 62
#define NTV (NT*NV)          // 15872
#define TOT (NB*NC*NT*NV)    // 32505856

// ---- device-global scratch (no runtime allocation allowed) ----
__device__ float g_anorm[NV*NV];
__device__ float g_Y[TOT];     // after graph mix + 1x1 conv
__device__ float g_Z[TOT];     // after temporal conv (incl. conv bias)
__device__ float g_sum1[NC], g_sq1[NC], g_sum2[NC], g_sq2[NC];
__device__ float g_s1[NC], g_t1[NC], g_s2[NC], g_t2[NC];

// ================= init: a_norm + zero stats ==================
__global__ void k_init(const float* __restrict__ adj) {
    __shared__ float dinv[NV];
    int tid = threadIdx.x;                       // 128 threads
    if (tid < NV) {
        float s = 1.0f;                          // self loop
        for (int w = 0; w < NV; ++w) s += adj[tid*NV + w];
        dinv[tid] = rsqrtf(s);
    }
    if (tid >= 64 && tid < 128) {
        int o = tid - 64;
        g_sum1[o] = 0.f; g_sq1[o] = 0.f; g_sum2[o] = 0.f; g_sq2[o] = 0.f;
    }
    __syncthreads();
    for (int e = tid; e < NV*NV; e += 128) {
        int v = e / NV, w = e % NV;
        float a = adj[e] + (v == w ? 1.0f : 0.0f);
        g_anorm[e] = a * dinv[v] * dinv[w];
    }
}

// ============ stage A: Y[b,o,t,v] = sum_c Wmlp[o,c] * sum_w x[b,c,t,w]*An[v,w] + b_mlp[o]
// one block per (b,t); two chained 64x64(x64-padded) smem GEMMs; BN1 stats accumulated.
__global__ void __launch_bounds__(256) k_stageA(const float* __restrict__ x,
                                                const float* __restrict__ w_mlp,
                                                const float* __restrict__ b_mlp) {
    __shared__ float sX[4096];   // x slice [c][w], w padded 62->64 with 0
    __shared__ float sB[4096];   // first a_norm [w][v] (symmetric), then w_mlp [o][c]
    __shared__ float sT[4096];   // tmp [c][v]

    const int t = blockIdx.x, b = blockIdx.y;
    const int tid = threadIdx.x;
    const float* xb = x + (size_t)b*NC*NTV + (size_t)t*NV;

    for (int e = tid; e < 4096; e += 256) {
        int r = e >> 6, q = e & 63;
        sX[e] = (q < NV) ? xb[r*NTV + q] : 0.f;                       // [c][w]
        sB[e] = (r < NV && q < NV) ? g_anorm[r*NV + q] : 0.f;         // [w][v]
    }
    __syncthreads();

    const int r0 = (tid >> 4) << 2;   // 4 rows (c, later o)
    const int v0 = (tid & 15) << 2;   // 4 cols (v)

    // ---- step 1: tmp[c][v] = sum_w sX[c][w] * sB[w][v]
    float acc[4][4] = {};
    #pragma unroll 4
    for (int w = 0; w < 64; ++w) {
        float4 bv = *(const float4*)&sB[(w << 6) + v0];
        float a0 = sX[((r0+0) << 6) + w];
        float a1 = sX[((r0+1) << 6) + w];
        float a2 = sX[((r0+2) << 6) + w];
        float a3 = sX[((r0+3) << 6) + w];
        acc[0][0]=fmaf(a0,bv.x,acc[0][0]); acc[0][1]=fmaf(a0,bv.y,acc[0][1]);
        acc[0][2]=fmaf(a0,bv.z,acc[0][2]); acc[0][3]=fmaf(a0,bv.w,acc[0][3]);
        acc[1][0]=fmaf(a1,bv.x,acc[1][0]); acc[1][1]=fmaf(a1,bv.y,acc[1][1]);
        acc[1][2]=fmaf(a1,bv.z,acc[1][2]); acc[1][3]=fmaf(a1,bv.w,acc[1][3]);
        acc[2][0]=fmaf(a2,bv.x,acc[2][0]); acc[2][1]=fmaf(a2,bv.y,acc[2][1]);
        acc[2][2]=fmaf(a2,bv.z,acc[2][2]); acc[2][3]=fmaf(a2,bv.w,acc[2][3]);
        acc[3][0]=fmaf(a3,bv.x,acc[3][0]); acc[3][1]=fmaf(a3,bv.y,acc[3][1]);
        acc[3][2]=fmaf(a3,bv.z,acc[3][2]); acc[3][3]=fmaf(a3,bv.w,acc[3][3]);
    }
    #pragma unroll
    for (int i = 0; i < 4; ++i)
        #pragma unroll
        for (int j = 0; j < 4; ++j)
            sT[((r0+i) << 6) + v0 + j] = acc[i][j];
    __syncthreads();                       // step1 reads of sB done
    for (int e = tid; e < 4096; e += 256) sB[e] = w_mlp[e];   // [o][c]
    __syncthreads();

    // ---- step 2: Y[o][v] = sum_c sB[o][c] * sT[c][v]
    float acc2[4][4] = {};
    #pragma unroll 4
    for (int c = 0; c < 64; ++c) {
        float4 bv = *(const float4*)&sT[(c << 6) + v0];
        float a0 = sB[((r0+0) << 6) + c];
        float a1 = sB[((r0+1) << 6) + c];
        float a2 = sB[((r0+2) << 6) + c];
        float a3 = sB[((r0+3) << 6) + c];
        acc2[0][0]=fmaf(a0,bv.x,acc2[0][0]); acc2[0][1]=fmaf(a0,bv.y,acc2[0][1]);
        acc2[0][2]=fmaf(a0,bv.z,acc2[0][2]); acc2[0][3]=fmaf(a0,bv.w,acc2[0][3]);
        acc2[1][0]=fmaf(a1,bv.x,acc2[1][0]); acc2[1][1]=fmaf(a1,bv.y,acc2[1][1]);
        acc2[1][2]=fmaf(a1,bv.z,acc2[1][2]); acc2[1][3]=fmaf(a1,bv.w,acc2[1][3]);
        acc2[2][0]=fmaf(a2,bv.x,acc2[2][0]); acc2[2][1]=fmaf(a2,bv.y,acc2[2][1]);
        acc2[2][2]=fmaf(a2,bv.z,acc2[2][2]); acc2[2][3]=fmaf(a2,bv.w,acc2[2][3]);
        acc2[3][0]=fmaf(a3,bv.x,acc2[3][0]); acc2[3][1]=fmaf(a3,bv.y,acc2[3][1]);
        acc2[3][2]=fmaf(a3,bv.z,acc2[3][2]); acc2[3][3]=fmaf(a3,bv.w,acc2[3][3]);
    }

    // ---- epilogue: bias, store Y, BN1 partial stats
    float psum[4] = {0,0,0,0}, psq[4] = {0,0,0,0};
    float* Yp = g_Y + (size_t)b*NC*NTV + (size_t)t*NV;
    #pragma unroll
    for (int i = 0; i < 4; ++i) {
        float bm = b_mlp[r0+i];
        #pragma unroll
        for (int j = 0; j < 4; ++j) {
            int v = v0 + j;
            if (v < NV) {
                float y = acc2[i][j] + bm;
                Yp[(r0+i)*NTV + v] = y;
                psum[i] += y; psq[i] += y*y;
            }
        }
    }
    // block reduction (sX reused as scratch: [o][16] sums, +1024 sumsq)
    #pragma unroll
    for (int i = 0; i < 4; ++i) {
        sX[(r0+i)*16 + (tid & 15)] = psum[i];
        sX[1024 + (r0+i)*16 + (tid & 15)] = psq[i];
    }
    __syncthreads();
    if (tid < 64) {
        float s = 0.f, q = 0.f;
        #pragma unroll
        for (int l = 0; l < 16; ++l) { s += sX[tid*16 + l]; q += sX[1024 + tid*16 + l]; }
        atomicAdd(&g_sum1[tid], s);
        atomicAdd(&g_sq1[tid], q);
    }
}

// ============ BN finalize: per-channel scale/shift from accumulated sums
__global__ void k_finalize(const float* __restrict__ gamma,
                           const float* __restrict__ beta, int which) {
    int o = threadIdx.x;   // 64 threads
    const float invN = 1.0f / (float)(NB*NT*NV);
    float sm = which ? g_sum2[o] : g_sum1[o];
    float sq = which ? g_sq2[o]  : g_sq1[o];
    float m = sm * invN;
    float var = fmaxf(sq * invN - m*m, 0.f);
    float sc = gamma[o] * rsqrtf(var + 1e-5f);
    float sh = beta[o] - m * sc;
    if (which) { g_s2[o] = sc; g_t2[o] = sh; }
    else       { g_s1[o] = sc; g_t1[o] = sh; }
}

// ============ stage B: temporal conv (K=9, pad 4) over BN1+ReLU(Y), + BN2 stats.
// Im2col GEMM: M=64(o), N=4t x 64v(pad) per block, K=576 in 8-channel chunks.
__global__ void __launch_bounds__(256, 2) k_stageB(const float* __restrict__ wconv,
                                                   const float* __restrict__ bconv) {
    __shared__ float sIn[8*12*64];   // [c'][tt(12 = 4+8 halo)][v(64 pad)]
    __shared__ float sW[64*72];      // [o][c'*9+k]

    const int t0 = blockIdx.x * 4;
    const int b  = blockIdx.y;
    const int tid = threadIdx.x;
    const int o0 = (tid >> 5) * 8;        // 8 o-rows per thread
    const int g  = tid & 31;
    const int tl = g >> 3;                // local t 0..3
    const int v0 = (g & 7) * 8;           // 8 v-cols per thread

    float acc[8][8] = {};

    for (int cc = 0; cc < NC; cc += 8) {
        __syncthreads();   // previous chunk's reads complete
        // input tile: BN1 affine + ReLU applied on load; t halo + v pad zeroed
        for (int e = tid; e < 8*12*64; e += 256) {
            int v  = e & 63;
            int rr = e >> 6;
            int tt = rr % 12;
            int c  = rr / 12;
            int gt = t0 - 4 + tt;
            float val = 0.f;
            if (v < NV && gt >= 0 && gt < NT) {
                float y = g_Y[((size_t)(b*NC + cc + c)*NT + gt)*NV + v];
                val = fmaxf(fmaf(y, g_s1[cc+c], g_t1[cc+c]), 0.f);
            }
            sIn[e] = val;
        }
        for (int e = tid; e < 64*72; e += 256) {
            int o = e / 72, r = e % 72;
            int c = r / 9,  k = r % 9;
            sW[e] = wconv[(o*NC + cc + c)*9 + k];
        }
        __syncthreads();

        #pragma unroll
        for (int c = 0; c < 8; ++c) {
            const float* irow = &sIn[(c*12 + tl)*64 + v0];
            #pragma unroll
            for (int k = 0; k < 9; ++k) {
                float a[8];
                #pragma unroll
                for (int i = 0; i < 8; ++i) a[i] = sW[(o0+i)*72 + c*9 + k];
                float4 b0 = *(const float4*)&irow[k*64];
                float4 b1 = *(const float4*)&irow[k*64 + 4];
                float bv[8] = {b0.x,b0.y,b0.z,b0.w,b1.x,b1.y,b1.z,b1.w};
                #pragma unroll
                for (int i = 0; i < 8; ++i)
                    #pragma unroll
                    for (int j = 0; j < 8; ++j)
                        acc[i][j] = fmaf(a[i], bv[j], acc[i][j]);
            }
        }
    }

    // epilogue: conv bias, store Z, BN2 partial stats
    float psum[8] = {}, psq[8] = {};
    const int t = t0 + tl;
    #pragma unroll
    for (int i = 0; i < 8; ++i) {
        int o = o0 + i;
        float bc = bconv[o];
        size_t base = ((size_t)(b*NC + o)*NT + t)*NV;
        #pragma unroll
        for (int j = 0; j < 8; ++j) {
            int v = v0 + j;
            if (v < NV) {
                float z = acc[i][j] + bc;
                g_Z[base + v] = z;
                psum[i] += z; psq[i] += z*z;
            }
        }
    }
    __syncthreads();   // all compute reads of sIn done before reuse
    #pragma unroll
    for (int i = 0; i < 8; ++i) {
        sIn[(o0+i)*32 + g] = psum[i];
        sIn[2048 + (o0+i)*32 + g] = psq[i];
    }
    __syncthreads();
    if (tid < 64) {
        float s = 0.f, q = 0.f;
        #pragma unroll
        for (int l = 0; l < 32; ++l) { s += sIn[tid*32 + l]; q += sIn[2048 + tid*32 + l]; }
        atomicAdd(&g_sum2[tid], s);
        atomicAdd(&g_sq2[tid], q);
    }
}

// ============ stage C: out = relu(BN2(Z) + x), vectorized float4
__global__ void k_stageC(const float* __restrict__ x, float* __restrict__ out) {
    int i = (blockIdx.x * 256 + threadIdx.x) * 4;
    if (i >= TOT) return;
    int o = (i / NTV) & 63;        // NTV multiple of 4 -> same o across the float4
    float s = g_s2[o], tt = g_t2[o];
    float4 z  = *(const float4*)&g_Z[i];
    float4 xv = *(const float4*)&x[i];
    float4 r;
    r.x = fmaxf(fmaf(z.x, s, tt) + xv.x, 0.f);
    r.y = fmaxf(fmaf(z.y, s, tt) + xv.y, 0.f);
    r.z = fmaxf(fmaf(z.z, s, tt) + xv.z, 0.f);
    r.w = fmaxf(fmaf(z.w, s, tt) + xv.w, 0.f);
    *(float4*)&out[i] = r;
}

extern "C" void kernel_launch(void* const* d_in, const int* in_sizes, int n_in,
                              void* d_out, int out_size) {
    const float* x      = (const float*)d_in[0];
    const float* adj    = (const float*)d_in[1];
    const float* w_mlp  = (const float*)d_in[2];
    const float* b_mlp  = (const float*)d_in[3];
    const float* g1     = (const float*)d_in[4];
    const float* b1     = (const float*)d_in[5];
    const float* w_conv = (const float*)d_in[6];
    const float* b_conv = (const float*)d_in[7];
    const float* g2     = (const float*)d_in[8];
    const float* b2     = (const float*)d_in[9];
    float* out = (float*)d_out;

    k_init<<<1, 128>>>(adj);
    k_stageA<<<dim3(NT, NB), 256>>>(x, w_mlp, b_mlp);
    k_finalize<<<1, 64>>>(g1, b1, 0);
    k_stageB<<<dim3(NT/4, NB), 256>>>(w_conv, b_conv);
    k_finalize<<<1, 64>>>(g2, b2, 1);
    k_stageC<<<TOT/4/256, 256>>>(x, out);
}

// round 6
// speedup vs baseline: 2.2027x; 2.2027x over previous
#include <cuda_runtime.h>
#include <cstdint>

#define NB 32
#define NC 64
#define NT 256
#define NV 62
#define NTV (NT*NV)          // 15872
#define TOT (NB*NC*NT*NV)    // 32505856

// ---- device-global scratch ----
__device__ float g_anorm[NV*NV];
__device__ __align__(16) float g_Ya[NB*NT*64*64];   // padded+transposed: [b][t][v64][c64]
__device__ __align__(16) float g_Z[TOT];            // conv out (+bias), [b][o][t][v]
__device__ __align__(16) float g_wr[9*64*64];       // weights [k][o][c]
__device__ float g_sum1[NC], g_sq1[NC], g_sum2[NC], g_sq2[NC];
__device__ float g_s1[NC], g_t1[NC], g_s2[NC], g_t2[NC];

// ---- mma.sync tf32 helpers (sm_80+, works on plain sm_100 target) ----
__device__ __forceinline__ uint32_t tf32_of(float f) {
    uint32_t u;
    asm("cvt.rna.tf32.f32 %0, %1;" : "=r"(u) : "f"(f));
    return u;
}
__device__ __forceinline__ void mma_tf32(float* d,
                                         uint32_t a0, uint32_t a1, uint32_t a2, uint32_t a3,
                                         uint32_t b0, uint32_t b1) {
    asm volatile("mma.sync.aligned.m16n8k8.row.col.f32.tf32.tf32.f32 "
                 "{%0,%1,%2,%3}, {%4,%5,%6,%7}, {%8,%9}, {%0,%1,%2,%3};"
                 : "+f"(d[0]), "+f"(d[1]), "+f"(d[2]), "+f"(d[3])
                 : "r"(a0), "r"(a1), "r"(a2), "r"(a3), "r"(b0), "r"(b1));
}

// ================= init: a_norm + zero stats ==================
__global__ void k_init(const float* __restrict__ adj) {
    __shared__ float dinv[NV];
    int tid = threadIdx.x;
    if (tid < NV) {
        float s = 1.0f;
        for (int w = 0; w < NV; ++w) s += adj[tid*NV + w];
        dinv[tid] = rsqrtf(s);
    }
    if (tid >= 64 && tid < 128) {
        int o = tid - 64;
        g_sum1[o] = 0.f; g_sq1[o] = 0.f; g_sum2[o] = 0.f; g_sq2[o] = 0.f;
    }
    __syncthreads();
    for (int e = tid; e < NV*NV; e += 128) {
        int v = e / NV, w = e % NV;
        float a = adj[e] + (v == w ? 1.0f : 0.0f);
        g_anorm[e] = a * dinv[v] * dinv[w];
    }
}

// ============ weight reorder: g_wr[k][o][c] = w_conv[o][c][k]
__global__ void k_wprep(const float* __restrict__ wconv) {
    int i = blockIdx.x * 256 + threadIdx.x;
    if (i < 9*64*64) {
        int c = i & 63, ko = i >> 6;
        int o = ko & 63, k = ko >> 6;
        g_wr[i] = wconv[(o*64 + c)*9 + k];
    }
}

// ============ stage A: graph mix + 1x1 conv; writes padded/transposed Ya; BN1 stats
__global__ void __launch_bounds__(256) k_stageA(const float* __restrict__ x,
                                                const float* __restrict__ w_mlp,
                                                const float* __restrict__ b_mlp) {
    __shared__ float sX[4096];
    __shared__ float sB[4096];
    __shared__ float sT[4096];

    const int t = blockIdx.x, b = blockIdx.y;
    const int tid = threadIdx.x;
    const float* xb = x + (size_t)b*NC*NTV + (size_t)t*NV;

    for (int e = tid; e < 4096; e += 256) {
        int r = e >> 6, q = e & 63;
        sX[e] = (q < NV) ? xb[r*NTV + q] : 0.f;
        sB[e] = (r < NV && q < NV) ? g_anorm[r*NV + q] : 0.f;
    }
    __syncthreads();

    const int r0 = (tid >> 4) << 2;
    const int v0 = (tid & 15) << 2;

    float acc[4][4] = {};
    #pragma unroll 4
    for (int w = 0; w < 64; ++w) {
        float4 bv = *(const float4*)&sB[(w << 6) + v0];
        float a0 = sX[((r0+0) << 6) + w];
        float a1 = sX[((r0+1) << 6) + w];
        float a2 = sX[((r0+2) << 6) + w];
        float a3 = sX[((r0+3) << 6) + w];
        acc[0][0]=fmaf(a0,bv.x,acc[0][0]); acc[0][1]=fmaf(a0,bv.y,acc[0][1]);
        acc[0][2]=fmaf(a0,bv.z,acc[0][2]); acc[0][3]=fmaf(a0,bv.w,acc[0][3]);
        acc[1][0]=fmaf(a1,bv.x,acc[1][0]); acc[1][1]=fmaf(a1,bv.y,acc[1][1]);
        acc[1][2]=fmaf(a1,bv.z,acc[1][2]); acc[1][3]=fmaf(a1,bv.w,acc[1][3]);
        acc[2][0]=fmaf(a2,bv.x,acc[2][0]); acc[2][1]=fmaf(a2,bv.y,acc[2][1]);
        acc[2][2]=fmaf(a2,bv.z,acc[2][2]); acc[2][3]=fmaf(a2,bv.w,acc[2][3]);
        acc[3][0]=fmaf(a3,bv.x,acc[3][0]); acc[3][1]=fmaf(a3,bv.y,acc[3][1]);
        acc[3][2]=fmaf(a3,bv.z,acc[3][2]); acc[3][3]=fmaf(a3,bv.w,acc[3][3]);
    }
    #pragma unroll
    for (int i = 0; i < 4; ++i)
        #pragma unroll
        for (int j = 0; j < 4; ++j)
            sT[((r0+i) << 6) + v0 + j] = acc[i][j];
    __syncthreads();
    for (int e = tid; e < 4096; e += 256) sB[e] = w_mlp[e];
    __syncthreads();

    float acc2[4][4] = {};
    #pragma unroll 4
    for (int c = 0; c < 64; ++c) {
        float4 bv = *(const float4*)&sT[(c << 6) + v0];
        float a0 = sB[((r0+0) << 6) + c];
        float a1 = sB[((r0+1) << 6) + c];
        float a2 = sB[((r0+2) << 6) + c];
        float a3 = sB[((r0+3) << 6) + c];
        acc2[0][0]=fmaf(a0,bv.x,acc2[0][0]); acc2[0][1]=fmaf(a0,bv.y,acc2[0][1]);
        acc2[0][2]=fmaf(a0,bv.z,acc2[0][2]); acc2[0][3]=fmaf(a0,bv.w,acc2[0][3]);
        acc2[1][0]=fmaf(a1,bv.x,acc2[1][0]); acc2[1][1]=fmaf(a1,bv.y,acc2[1][1]);
        acc2[1][2]=fmaf(a1,bv.z,acc2[1][2]); acc2[1][3]=fmaf(a1,bv.w,acc2[1][3]);
        acc2[2][0]=fmaf(a2,bv.x,acc2[2][0]); acc2[2][1]=fmaf(a2,bv.y,acc2[2][1]);
        acc2[2][2]=fmaf(a2,bv.z,acc2[2][2]); acc2[2][3]=fmaf(a2,bv.w,acc2[2][3]);
        acc2[3][0]=fmaf(a3,bv.x,acc2[3][0]); acc2[3][1]=fmaf(a3,bv.y,acc2[3][1]);
        acc2[3][2]=fmaf(a3,bv.z,acc2[3][2]); acc2[3][3]=fmaf(a3,bv.w,acc2[3][3]);
    }

    float yv[4][4];
    #pragma unroll
    for (int i = 0; i < 4; ++i) {
        float bm = b_mlp[r0 + i];
        #pragma unroll
        for (int j = 0; j < 4; ++j) yv[i][j] = acc2[i][j] + bm;
    }
    float* Yp = g_Ya + ((size_t)(b*NT + t) << 12);
    #pragma unroll
    for (int j = 0; j < 4; ++j) {
        float4 o4 = make_float4(yv[0][j], yv[1][j], yv[2][j], yv[3][j]);
        *(float4*)&Yp[(v0 + j)*64 + r0] = o4;
    }
    float psum[4] = {0,0,0,0}, psq[4] = {0,0,0,0};
    #pragma unroll
    for (int i = 0; i < 4; ++i)
        #pragma unroll
        for (int j = 0; j < 4; ++j)
            if (v0 + j < NV) { psum[i] += yv[i][j]; psq[i] += yv[i][j]*yv[i][j]; }

    #pragma unroll
    for (int i = 0; i < 4; ++i) {
        sX[(r0+i)*16 + (tid & 15)] = psum[i];
        sX[1024 + (r0+i)*16 + (tid & 15)] = psq[i];
    }
    __syncthreads();
    if (tid < 64) {
        float s = 0.f, q = 0.f;
        #pragma unroll
        for (int l = 0; l < 16; ++l) { s += sX[tid*16 + l]; q += sX[1024 + tid*16 + l]; }
        atomicAdd(&g_sum1[tid], s);
        atomicAdd(&g_sq1[tid], q);
    }
}

// ============ BN finalize
__global__ void k_finalize(const float* __restrict__ gamma,
                           const float* __restrict__ beta, int which) {
    int o = threadIdx.x;
    const float invN = 1.0f / (float)(NB*NT*NV);
    float sm = which ? g_sum2[o] : g_sum1[o];
    float sq = which ? g_sq2[o]  : g_sq1[o];
    float m = sm * invN;
    float var = fmaxf(sq * invN - m*m, 0.f);
    float sc = gamma[o] * rsqrtf(var + 1e-5f);
    float sh = beta[o] - m * sc;
    if (which) { g_s2[o] = sc; g_t2[o] = sh; }
    else       { g_s1[o] = sc; g_t1[o] = sh; }
}

// ============ stage B (mma.sync tf32): temporal conv K=9 as 9 shifted GEMM accums.
// Block = (b, 8 output t's). M=512 rows (t,v-pad64), N=64 (o), K=576 in 4 c-chunks of 16.
// Warp w owns t-local = w: 4 m16 tiles x 8 n8 tiles, acc in regs.
// SMEM rows padded to 20 floats -> all fragment LDS patterns bank-conflict-free.
#define T_TILE 8
#define PADR 20
#define SA_FLOATS (16*64*PADR)      // 20480
#define SW_FLOATS (9*64*PADR)       // 11520
#define SMEM_FLOATS (SA_FLOATS + SW_FLOATS + 192)
#define SMEM_BYTES (SMEM_FLOATS*4)

__global__ void __launch_bounds__(256, 1) k_stageB_mma(const float* __restrict__ bconv) {
    extern __shared__ float sm[];
    float* sA  = sm;                          // [tt*64+v][20]  (tf32 bits)
    float* sW  = sm + SA_FLOATS;              // [tap*64+o][20] (tf32 bits)
    float* s1v = sm + SA_FLOATS + SW_FLOATS;  // 64
    float* t1v = s1v + 64;
    float* sbc = t1v + 64;

    const int tid  = threadIdx.x;
    const int wid  = tid >> 5;
    const int lane = tid & 31;
    const int gid  = lane >> 2;
    const int tid4 = lane & 3;
    const int t0   = blockIdx.x * T_TILE;
    const int b    = blockIdx.y;

    if (tid < 64) { s1v[tid] = g_s1[tid]; t1v[tid] = g_t1[tid]; sbc[tid] = bconv[tid]; }

    float acc[4][8][4];
    #pragma unroll
    for (int mt = 0; mt < 4; ++mt)
        #pragma unroll
        for (int n8 = 0; n8 < 8; ++n8)
            #pragma unroll
            for (int r = 0; r < 4; ++r) acc[mt][n8][r] = 0.f;

    for (int ch = 0; ch < 4; ++ch) {
        const int c0 = ch * 16;
        __syncthreads();   // prior reads of sA/sW done; also covers s1v init
        // ---- stage A tile: BN1 affine + ReLU + tf32 convert; t-halo zeroed
        for (int e = tid; e < 16*64*4; e += 256) {
            int cq  = e & 3;
            int row = e >> 2;            // tt*64 + v
            int v = row & 63, tt = row >> 6;
            int t = t0 - 4 + tt;
            float4 val = make_float4(0.f, 0.f, 0.f, 0.f);
            if (t >= 0 && t < NT) {
                const float* yp = &g_Ya[(((size_t)(b*NT + t) << 6) + v)*64 + c0 + cq*4];
                float4 y  = *(const float4*)yp;
                float4 s  = *(const float4*)&s1v[c0 + cq*4];
                float4 sh = *(const float4*)&t1v[c0 + cq*4];
                val.x = fmaxf(fmaf(y.x, s.x, sh.x), 0.f);
                val.y = fmaxf(fmaf(y.y, s.y, sh.y), 0.f);
                val.z = fmaxf(fmaf(y.z, s.z, sh.z), 0.f);
                val.w = fmaxf(fmaf(y.w, s.w, sh.w), 0.f);
            }
            float4 o4;
            o4.x = __uint_as_float(tf32_of(val.x));
            o4.y = __uint_as_float(tf32_of(val.y));
            o4.z = __uint_as_float(tf32_of(val.z));
            o4.w = __uint_as_float(tf32_of(val.w));
            *(float4*)&sA[row*PADR + cq*4] = o4;
        }
        // ---- stage W tile: tf32 convert
        for (int e = tid; e < 9*64*4; e += 256) {
            int cq = e & 3;
            int r  = e >> 2;             // tap*64 + o
            float4 w = *(const float4*)&g_wr[(size_t)r*64 + c0 + cq*4];
            float4 o4;
            o4.x = __uint_as_float(tf32_of(w.x));
            o4.y = __uint_as_float(tf32_of(w.y));
            o4.z = __uint_as_float(tf32_of(w.z));
            o4.w = __uint_as_float(tf32_of(w.w));
            *(float4*)&sW[r*PADR + cq*4] = o4;
        }
        __syncthreads();

        // ---- compute: 9 taps x 2 k8 x (4 m16 x 8 n8) mma
        for (int tap = 0; tap < 9; ++tap) {
            const int arow_base = (wid + tap)*64;
            #pragma unroll
            for (int k8 = 0; k8 < 2; ++k8) {
                const int ccol = k8*8 + tid4;
                uint32_t bf[8][2];
                #pragma unroll
                for (int n8 = 0; n8 < 8; ++n8) {
                    const float* wp = &sW[(tap*64 + n8*8 + gid)*PADR + ccol];
                    bf[n8][0] = __float_as_uint(wp[0]);
                    bf[n8][1] = __float_as_uint(wp[4]);
                }
                #pragma unroll
                for (int mt = 0; mt < 4; ++mt) {
                    const float* ap = &sA[(arow_base + mt*16 + gid)*PADR + ccol];
                    uint32_t a0 = __float_as_uint(ap[0]);
                    uint32_t a1 = __float_as_uint(ap[8*PADR]);
                    uint32_t a2 = __float_as_uint(ap[4]);
                    uint32_t a3 = __float_as_uint(ap[8*PADR + 4]);
                    #pragma unroll
                    for (int n8 = 0; n8 < 8; ++n8)
                        mma_tf32(acc[mt][n8], a0, a1, a2, a3, bf[n8][0], bf[n8][1]);
                }
            }
        }
    }

    // ---- epilogue: D[(t,v), o] -> Z[b][o][t][v] + conv bias (v<62 only)
    const int t = t0 + wid;
    #pragma unroll
    for (int mt = 0; mt < 4; ++mt) {
        const int v0 = mt*16 + gid;      // always < 56 < NV
        const int v1 = v0 + 8;
        #pragma unroll
        for (int n8 = 0; n8 < 8; ++n8) {
            const int o = n8*8 + tid4*2;
            const float b0 = sbc[o], b1 = sbc[o+1];
            const size_t base0 = ((size_t)(b*NC + o)*NT + t)*NV;
            const size_t base1 = base0 + (size_t)NT*NV;
            g_Z[base0 + v0] = acc[mt][n8][0] + b0;
            g_Z[base1 + v0] = acc[mt][n8][1] + b1;
            if (v1 < NV) {
                g_Z[base0 + v1] = acc[mt][n8][2] + b0;
                g_Z[base1 + v1] = acc[mt][n8][3] + b1;
            }
        }
    }
}

// ============ BN2 stats pass over Z
__global__ void k_stats2() {
    __shared__ float rs[256], rq[256];
    const float4* p = (const float4*)(g_Z + (size_t)blockIdx.x * NTV);
    float s = 0.f, q = 0.f;
    for (int i = threadIdx.x; i < NTV/4; i += 256) {
        float4 z = p[i];
        s += z.x + z.y + z.z + z.w;
        q += z.x*z.x + z.y*z.y + z.z*z.z + z.w*z.w;
    }
    rs[threadIdx.x] = s; rq[threadIdx.x] = q;
    __syncthreads();
    for (int st = 128; st > 0; st >>= 1) {
        if (threadIdx.x < st) { rs[threadIdx.x] += rs[threadIdx.x+st]; rq[threadIdx.x] += rq[threadIdx.x+st]; }
        __syncthreads();
    }
    if (threadIdx.x == 0) {
        atomicAdd(&g_sum2[blockIdx.x & 63], rs[0]);
        atomicAdd(&g_sq2[blockIdx.x & 63], rq[0]);
    }
}

// ============ stage C: out = relu(BN2(Z) + x)
__global__ void k_stageC(const float* __restrict__ x, float* __restrict__ out) {
    int i = (blockIdx.x * 256 + threadIdx.x) * 4;
    if (i >= TOT) return;
    int o = (i / NTV) & 63;
    float s = g_s2[o], tt = g_t2[o];
    float4 z  = *(const float4*)&g_Z[i];
    float4 xv = *(const float4*)&x[i];
    float4 r;
    r.x = fmaxf(fmaf(z.x, s, tt) + xv.x, 0.f);
    r.y = fmaxf(fmaf(z.y, s, tt) + xv.y, 0.f);
    r.z = fmaxf(fmaf(z.z, s, tt) + xv.z, 0.f);
    r.w = fmaxf(fmaf(z.w, s, tt) + xv.w, 0.f);
    *(float4*)&out[i] = r;
}

extern "C" void kernel_launch(void* const* d_in, const int* in_sizes, int n_in,
                              void* d_out, int out_size) {
    const float* x      = (const float*)d_in[0];
    const float* adj    = (const float*)d_in[1];
    const float* w_mlp  = (const float*)d_in[2];
    const float* b_mlp  = (const float*)d_in[3];
    const float* g1     = (const float*)d_in[4];
    const float* b1     = (const float*)d_in[5];
    const float* w_conv = (const float*)d_in[6];
    const float* b_conv = (const float*)d_in[7];
    const float* g2     = (const float*)d_in[8];
    const float* b2     = (const float*)d_in[9];
    float* out = (float*)d_out;

    cudaFuncSetAttribute(k_stageB_mma, cudaFuncAttributeMaxDynamicSharedMemorySize, SMEM_BYTES);

    k_init<<<1, 128>>>(adj);
    k_wprep<<<144, 256>>>(w_conv);
    k_stageA<<<dim3(NT, NB), 256>>>(x, w_mlp, b_mlp);
    k_finalize<<<1, 64>>>(g1, b1, 0);
    k_stageB_mma<<<dim3(NT/T_TILE, NB), 256, SMEM_BYTES>>>(b_conv);
    k_stats2<<<NB*NC, 256>>>();
    k_finalize<<<1, 64>>>(g2, b2, 1);
    k_stageC<<<TOT/4/256, 256>>>(x, out);
}

// round 7
// speedup vs baseline: 2.5477x; 1.1566x over previous
#include <cuda_runtime.h>
#include <cstdint>

#define NB 32
#define NC 64
#define NT 256
#define NV 62
#define NTV (NT*NV)          // 15872
#define TOT (NB*NC*NT*NV)    // 32505856

// ---- device-global scratch ----
__device__ float g_anorm[NV*NV];
__device__ __align__(16) float g_Ya[NB*NT*64*64];   // padded+transposed: [b][t][v64][o64]
__device__ __align__(16) float g_Z[TOT];            // conv out (+bias), [b][o][t][v]
__device__ __align__(16) float g_wr[9*64*64];       // weights [k][o][c]
__device__ float g_sum1[NC], g_sq1[NC], g_sum2[NC], g_sq2[NC];
__device__ float g_s1[NC], g_t1[NC], g_s2[NC], g_t2[NC];

// ---- mma.sync tf32 helpers (sm_80+, valid on plain sm_100 target) ----
__device__ __forceinline__ uint32_t tf32_of(float f) {
    uint32_t u;
    asm("cvt.rna.tf32.f32 %0, %1;" : "=r"(u) : "f"(f));
    return u;
}
__device__ __forceinline__ void mma_tf32(float* d,
                                         uint32_t a0, uint32_t a1, uint32_t a2, uint32_t a3,
                                         uint32_t b0, uint32_t b1) {
    asm volatile("mma.sync.aligned.m16n8k8.row.col.f32.tf32.tf32.f32 "
                 "{%0,%1,%2,%3}, {%4,%5,%6,%7}, {%8,%9}, {%0,%1,%2,%3};"
                 : "+f"(d[0]), "+f"(d[1]), "+f"(d[2]), "+f"(d[3])
                 : "r"(a0), "r"(a1), "r"(a2), "r"(a3), "r"(b0), "r"(b1));
}

// ================= init: a_norm + zero stats ==================
__global__ void k_init(const float* __restrict__ adj) {
    __shared__ float dinv[NV];
    int tid = threadIdx.x;
    if (tid < NV) {
        float s = 1.0f;
        for (int w = 0; w < NV; ++w) s += adj[tid*NV + w];
        dinv[tid] = rsqrtf(s);
    }
    if (tid >= 64 && tid < 128) {
        int o = tid - 64;
        g_sum1[o] = 0.f; g_sq1[o] = 0.f; g_sum2[o] = 0.f; g_sq2[o] = 0.f;
    }
    __syncthreads();
    for (int e = tid; e < NV*NV; e += 128) {
        int v = e / NV, w = e % NV;
        float a = adj[e] + (v == w ? 1.0f : 0.0f);
        g_anorm[e] = a * dinv[v] * dinv[w];
    }
}

// ============ weight reorder: g_wr[k][o][c] = w_conv[o][c][k]
__global__ void k_wprep(const float* __restrict__ wconv) {
    int i = blockIdx.x * 256 + threadIdx.x;
    if (i < 9*64*64) {
        int c = i & 63, ko = i >> 6;
        int o = ko & 63, k = ko >> 6;
        g_wr[i] = wconv[(o*64 + c)*9 + k];
    }
}

// ============ stage A (mma.sync tf32): per block (b, 2 t's)
// GEMM1: T1t[v][n=(tl,c)] = An[v][w] * X[(tl,c)][w]^T   (M=64, N=128, K=64)
// GEMM2 (per tl): Y[v][o]  = T1t[v][c] * W[o][c]^T       (M=64, N=64,  K=64)
// Output Y[v][o] == Ya layout directly. BN1 stats fused.
#define TA 2
#define A_AN 0                      // [64][68]
#define A_X  (A_AN + 64*68)         // [128][68]
#define A_W  (A_X + 128*68)         // [64][68]
#define A_T  (A_W + 64*68)          // [64][132]
#define A_SUM (A_T + 64*132)        // [64]
#define A_SQ  (A_SUM + 64)          // [64]
#define A_BM  (A_SQ + 64)           // [64]
#define A_FLOATS (A_BM + 64)
#define A_BYTES (A_FLOATS*4)

__global__ void __launch_bounds__(256, 2) k_stageA_mma(const float* __restrict__ x,
                                                       const float* __restrict__ w_mlp,
                                                       const float* __restrict__ b_mlp) {
    extern __shared__ float sa[];
    float* sAn = sa + A_AN;
    float* sX  = sa + A_X;
    float* sW  = sa + A_W;
    float* sT  = sa + A_T;
    float* ssum = sa + A_SUM;
    float* ssq  = sa + A_SQ;
    float* sbm  = sa + A_BM;

    const int tid  = threadIdx.x;
    const int wid  = tid >> 5;
    const int lane = tid & 31;
    const int gid  = lane >> 2;
    const int tid4 = lane & 3;
    const int t0 = blockIdx.x * TA;
    const int b  = blockIdx.y;

    if (tid < 64) { ssum[tid] = 0.f; ssq[tid] = 0.f; sbm[tid] = b_mlp[tid]; }
    // An (zero-padded 62->64, tf32)
    for (int e = tid; e < 64*64; e += 256) {
        int w = e & 63, v = e >> 6;
        float val = (v < NV && w < NV) ? g_anorm[v*NV + w] : 0.f;
        sAn[v*68 + w] = __uint_as_float(tf32_of(val));
    }
    // X slice rows n = tl*64+c, cols w (tf32, w-pad zeroed)
    for (int e = tid; e < 128*64; e += 256) {
        int w = e & 63, n = e >> 6;
        int tl = n >> 6, c = n & 63;
        float val = (w < NV) ? x[((size_t)(b*NC + c)*NT + t0 + tl)*NV + w] : 0.f;
        sX[n*68 + w] = __uint_as_float(tf32_of(val));
    }
    // W rows o, cols c (tf32)
    for (int e = tid; e < 64*64; e += 256) {
        int c = e & 63, o = e >> 6;
        sW[o*68 + c] = __uint_as_float(tf32_of(w_mlp[o*64 + c]));
    }
    __syncthreads();

    // ---- GEMM1: warp handles mtile = wid&3 (v rows), n8 tiles nb0..nb0+7
    {
        const int mtile = wid & 3;
        const int nb0 = (wid >> 2) * 8;
        float acc[8][4];
        #pragma unroll
        for (int j = 0; j < 8; ++j)
            #pragma unroll
            for (int r = 0; r < 4; ++r) acc[j][r] = 0.f;

        #pragma unroll
        for (int k8 = 0; k8 < 8; ++k8) {
            const int col = k8*8 + tid4;
            const float* ap = &sAn[(mtile*16 + gid)*68 + col];
            uint32_t a0 = __float_as_uint(ap[0]);
            uint32_t a1 = __float_as_uint(ap[8*68]);
            uint32_t a2 = __float_as_uint(ap[4]);
            uint32_t a3 = __float_as_uint(ap[8*68 + 4]);
            #pragma unroll
            for (int j = 0; j < 8; ++j) {
                const float* bp = &sX[((nb0 + j)*8 + gid)*68 + col];
                mma_tf32(acc[j], a0, a1, a2, a3,
                         __float_as_uint(bp[0]), __float_as_uint(bp[4]));
            }
        }
        // write T1t
        #pragma unroll
        for (int j = 0; j < 8; ++j) {
            const int n = (nb0 + j)*8 + tid4*2;
            const int r = mtile*16 + gid;
            sT[r*132 + n]     = acc[j][0];
            sT[r*132 + n + 1] = acc[j][1];
            sT[(r+8)*132 + n]     = acc[j][2];
            sT[(r+8)*132 + n + 1] = acc[j][3];
        }
    }
    __syncthreads();

    // ---- GEMM2: warp handles tl = wid>>2, mtile = wid&3, all 8 n8 (o)
    {
        const int tl = wid >> 2;
        const int mtile = wid & 3;
        float acc[8][4];
        #pragma unroll
        for (int j = 0; j < 8; ++j)
            #pragma unroll
            for (int r = 0; r < 4; ++r) acc[j][r] = 0.f;

        #pragma unroll
        for (int k8 = 0; k8 < 8; ++k8) {
            const int colA = tl*64 + k8*8 + tid4;
            const float* ap = &sT[(mtile*16 + gid)*132 + colA];
            uint32_t a0 = tf32_of(ap[0]);
            uint32_t a1 = tf32_of(ap[8*132]);
            uint32_t a2 = tf32_of(ap[4]);
            uint32_t a3 = tf32_of(ap[8*132 + 4]);
            const int colB = k8*8 + tid4;
            #pragma unroll
            for (int j = 0; j < 8; ++j) {
                const float* bp = &sW[(j*8 + gid)*68 + colB];
                mma_tf32(acc[j], a0, a1, a2, a3,
                         __float_as_uint(bp[0]), __float_as_uint(bp[4]));
            }
        }

        // ---- epilogue: bias, store Ya[b][t][v][o], BN1 stats (v<62)
        const int t = t0 + tl;
        float* Yp = g_Ya + ((size_t)(b*NT + t) << 12);
        const int r0 = mtile*16 + gid;       // <= 55, always valid
        const int r1 = r0 + 8;               // mask r1 < 62 for stats
        const bool m1 = (r1 < NV);
        #pragma unroll
        for (int j = 0; j < 8; ++j) {
            const int o = j*8 + tid4*2;
            const float bm0 = sbm[o], bm1 = sbm[o+1];
            float y00 = acc[j][0] + bm0, y01 = acc[j][1] + bm1;
            float y10 = acc[j][2] + bm0, y11 = acc[j][3] + bm1;
            *(float2*)&Yp[r0*64 + o] = make_float2(y00, y01);
            *(float2*)&Yp[r1*64 + o] = make_float2(y10, y11);
            float s0 = y00 + (m1 ? y10 : 0.f);
            float q0 = y00*y00 + (m1 ? y10*y10 : 0.f);
            float s1 = y01 + (m1 ? y11 : 0.f);
            float q1 = y01*y01 + (m1 ? y11*y11 : 0.f);
            #pragma unroll
            for (int d = 4; d < 32; d <<= 1) {
                s0 += __shfl_xor_sync(0xFFFFFFFFu, s0, d);
                q0 += __shfl_xor_sync(0xFFFFFFFFu, q0, d);
                s1 += __shfl_xor_sync(0xFFFFFFFFu, s1, d);
                q1 += __shfl_xor_sync(0xFFFFFFFFu, q1, d);
            }
            if (lane < 4) {
                atomicAdd(&ssum[o], s0);   atomicAdd(&ssq[o], q0);
                atomicAdd(&ssum[o+1], s1); atomicAdd(&ssq[o+1], q1);
            }
        }
    }
    __syncthreads();
    if (tid < 64) {
        atomicAdd(&g_sum1[tid], ssum[tid]);
        atomicAdd(&g_sq1[tid], ssq[tid]);
    }
}

// ============ BN finalize
__global__ void k_finalize(const float* __restrict__ gamma,
                           const float* __restrict__ beta, int which) {
    int o = threadIdx.x;
    const float invN = 1.0f / (float)(NB*NT*NV);
    float sm = which ? g_sum2[o] : g_sum1[o];
    float sq = which ? g_sq2[o]  : g_sq1[o];
    float m = sm * invN;
    float var = fmaxf(sq * invN - m*m, 0.f);
    float sc = gamma[o] * rsqrtf(var + 1e-5f);
    float sh = beta[o] - m * sc;
    if (which) { g_s2[o] = sc; g_t2[o] = sh; }
    else       { g_s1[o] = sc; g_t1[o] = sh; }
}

// ============ stage B (mma.sync tf32): temporal conv K=9 as 9 shifted GEMM accums.
// Block = (b, 8 output t's). M=512 rows (t,v-pad64), N=64 (o), K=576 in 4 c-chunks of 16.
// BN2 stats fused into the epilogue (shfl + shared atomics).
#define T_TILE 8
#define PADR 20
#define SA_FLOATS (16*64*PADR)      // 20480
#define SW_FLOATS (9*64*PADR)       // 11520
#define SMEM_FLOATS (SA_FLOATS + SW_FLOATS + 320)
#define SMEM_BYTES (SMEM_FLOATS*4)

__global__ void __launch_bounds__(256, 1) k_stageB_mma(const float* __restrict__ bconv) {
    extern __shared__ float sm[];
    float* sA  = sm;                          // [tt*64+v][20]  (tf32 bits)
    float* sW  = sm + SA_FLOATS;              // [tap*64+o][20] (tf32 bits)
    float* s1v = sm + SA_FLOATS + SW_FLOATS;  // 64
    float* t1v = s1v + 64;
    float* sbc = t1v + 64;
    float* zsum = sbc + 64;
    float* zsq  = zsum + 64;

    const int tid  = threadIdx.x;
    const int wid  = tid >> 5;
    const int lane = tid & 31;
    const int gid  = lane >> 2;
    const int tid4 = lane & 3;
    const int t0   = blockIdx.x * T_TILE;
    const int b    = blockIdx.y;

    if (tid < 64) {
        s1v[tid] = g_s1[tid]; t1v[tid] = g_t1[tid]; sbc[tid] = bconv[tid];
        zsum[tid] = 0.f; zsq[tid] = 0.f;
    }

    float acc[4][8][4];
    #pragma unroll
    for (int mt = 0; mt < 4; ++mt)
        #pragma unroll
        for (int n8 = 0; n8 < 8; ++n8)
            #pragma unroll
            for (int r = 0; r < 4; ++r) acc[mt][n8][r] = 0.f;

    for (int ch = 0; ch < 4; ++ch) {
        const int c0 = ch * 16;
        __syncthreads();
        for (int e = tid; e < 16*64*4; e += 256) {
            int cq  = e & 3;
            int row = e >> 2;            // tt*64 + v
            int v = row & 63, tt = row >> 6;
            int t = t0 - 4 + tt;
            float4 val = make_float4(0.f, 0.f, 0.f, 0.f);
            if (t >= 0 && t < NT) {
                const float* yp = &g_Ya[(((size_t)(b*NT + t) << 6) + v)*64 + c0 + cq*4];
                float4 y  = *(const float4*)yp;
                float4 s  = *(const float4*)&s1v[c0 + cq*4];
                float4 sh = *(const float4*)&t1v[c0 + cq*4];
                val.x = fmaxf(fmaf(y.x, s.x, sh.x), 0.f);
                val.y = fmaxf(fmaf(y.y, s.y, sh.y), 0.f);
                val.z = fmaxf(fmaf(y.z, s.z, sh.z), 0.f);
                val.w = fmaxf(fmaf(y.w, s.w, sh.w), 0.f);
            }
            float4 o4;
            o4.x = __uint_as_float(tf32_of(val.x));
            o4.y = __uint_as_float(tf32_of(val.y));
            o4.z = __uint_as_float(tf32_of(val.z));
            o4.w = __uint_as_float(tf32_of(val.w));
            *(float4*)&sA[row*PADR + cq*4] = o4;
        }
        for (int e = tid; e < 9*64*4; e += 256) {
            int cq = e & 3;
            int r  = e >> 2;             // tap*64 + o
            float4 w = *(const float4*)&g_wr[(size_t)r*64 + c0 + cq*4];
            float4 o4;
            o4.x = __uint_as_float(tf32_of(w.x));
            o4.y = __uint_as_float(tf32_of(w.y));
            o4.z = __uint_as_float(tf32_of(w.z));
            o4.w = __uint_as_float(tf32_of(w.w));
            *(float4*)&sW[r*PADR + cq*4] = o4;
        }
        __syncthreads();

        for (int tap = 0; tap < 9; ++tap) {
            const int arow_base = (wid + tap)*64;
            #pragma unroll
            for (int k8 = 0; k8 < 2; ++k8) {
                const int ccol = k8*8 + tid4;
                uint32_t bf[8][2];
                #pragma unroll
                for (int n8 = 0; n8 < 8; ++n8) {
                    const float* wp = &sW[(tap*64 + n8*8 + gid)*PADR + ccol];
                    bf[n8][0] = __float_as_uint(wp[0]);
                    bf[n8][1] = __float_as_uint(wp[4]);
                }
                #pragma unroll
                for (int mt = 0; mt < 4; ++mt) {
                    const float* ap = &sA[(arow_base + mt*16 + gid)*PADR + ccol];
                    uint32_t a0 = __float_as_uint(ap[0]);
                    uint32_t a1 = __float_as_uint(ap[8*PADR]);
                    uint32_t a2 = __float_as_uint(ap[4]);
                    uint32_t a3 = __float_as_uint(ap[8*PADR + 4]);
                    #pragma unroll
                    for (int n8 = 0; n8 < 8; ++n8)
                        mma_tf32(acc[mt][n8], a0, a1, a2, a3, bf[n8][0], bf[n8][1]);
                }
            }
        }
    }

    // ---- epilogue: Z store (+bias) AND BN2 partial stats
    const int t = t0 + wid;
    #pragma unroll
    for (int n8 = 0; n8 < 8; ++n8) {
        const int o = n8*8 + tid4*2;
        const float b0 = sbc[o], b1 = sbc[o+1];
        const size_t base0 = ((size_t)(b*NC + o)*NT + t)*NV;
        const size_t base1 = base0 + (size_t)NT*NV;
        float s0 = 0.f, q0 = 0.f, s1 = 0.f, q1 = 0.f;
        #pragma unroll
        for (int mt = 0; mt < 4; ++mt) {
            const int v0 = mt*16 + gid;      // <= 55, always < NV
            const int v1 = v0 + 8;
            float z00 = acc[mt][n8][0] + b0, z01 = acc[mt][n8][1] + b1;
            g_Z[base0 + v0] = z00;
            g_Z[base1 + v0] = z01;
            s0 += z00; q0 += z00*z00; s1 += z01; q1 += z01*z01;
            if (v1 < NV) {
                float z10 = acc[mt][n8][2] + b0, z11 = acc[mt][n8][3] + b1;
                g_Z[base0 + v1] = z10;
                g_Z[base1 + v1] = z11;
                s0 += z10; q0 += z10*z10; s1 += z11; q1 += z11*z11;
            }
        }
        #pragma unroll
        for (int d = 4; d < 32; d <<= 1) {
            s0 += __shfl_xor_sync(0xFFFFFFFFu, s0, d);
            q0 += __shfl_xor_sync(0xFFFFFFFFu, q0, d);
            s1 += __shfl_xor_sync(0xFFFFFFFFu, s1, d);
            q1 += __shfl_xor_sync(0xFFFFFFFFu, q1, d);
        }
        if (lane < 4) {
            atomicAdd(&zsum[o], s0);   atomicAdd(&zsq[o], q0);
            atomicAdd(&zsum[o+1], s1); atomicAdd(&zsq[o+1], q1);
        }
    }
    __syncthreads();
    if (tid < 64) {
        atomicAdd(&g_sum2[tid], zsum[tid]);
        atomicAdd(&g_sq2[tid], zsq[tid]);
    }
}

// ============ stage C: out = relu(BN2(Z) + x)
__global__ void k_stageC(const float* __restrict__ x, float* __restrict__ out) {
    int i = (blockIdx.x * 256 + threadIdx.x) * 4;
    if (i >= TOT) return;
    int o = (i / NTV) & 63;
    float s = g_s2[o], tt = g_t2[o];
    float4 z  = *(const float4*)&g_Z[i];
    float4 xv = *(const float4*)&x[i];
    float4 r;
    r.x = fmaxf(fmaf(z.x, s, tt) + xv.x, 0.f);
    r.y = fmaxf(fmaf(z.y, s, tt) + xv.y, 0.f);
    r.z = fmaxf(fmaf(z.z, s, tt) + xv.z, 0.f);
    r.w = fmaxf(fmaf(z.w, s, tt) + xv.w, 0.f);
    *(float4*)&out[i] = r;
}

extern "C" void kernel_launch(void* const* d_in, const int* in_sizes, int n_in,
                              void* d_out, int out_size) {
    const float* x      = (const float*)d_in[0];
    const float* adj    = (const float*)d_in[1];
    const float* w_mlp  = (const float*)d_in[2];
    const float* b_mlp  = (const float*)d_in[3];
    const float* g1     = (const float*)d_in[4];
    const float* b1     = (const float*)d_in[5];
    const float* w_conv = (const float*)d_in[6];
    const float* b_conv = (const float*)d_in[7];
    const float* g2     = (const float*)d_in[8];
    const float* b2     = (const float*)d_in[9];
    float* out = (float*)d_out;

    cudaFuncSetAttribute(k_stageA_mma, cudaFuncAttributeMaxDynamicSharedMemorySize, A_BYTES);
    cudaFuncSetAttribute(k_stageB_mma, cudaFuncAttributeMaxDynamicSharedMemorySize, SMEM_BYTES);

    k_init<<<1, 128>>>(adj);
    k_wprep<<<144, 256>>>(w_conv);
    k_stageA_mma<<<dim3(NT/TA, NB), 256, A_BYTES>>>(x, w_mlp, b_mlp);
    k_finalize<<<1, 64>>>(g1, b1, 0);
    k_stageB_mma<<<dim3(NT/T_TILE, NB), 256, SMEM_BYTES>>>(b_conv);
    k_finalize<<<1, 64>>>(g2, b2, 1);
    k_stageC<<<TOT/4/256, 256>>>(x, out);
}

// round 9
// speedup vs baseline: 2.8096x; 1.1028x over previous
#include <cuda_runtime.h>
#include <cuda_fp16.h>
#include <cstdint>

#define NB 32
#define NC 64
#define NT 256
#define NV 62
#define NTV (NT*NV)          // 15872
#define TOT (NB*NC*NT*NV)    // 32505856

// ---- device-global scratch ----
__device__ float g_anorm[NV*NV];
__device__ __align__(16) float g_Ya[NB*NT*64*64];   // padded+transposed: [b][t][v64][c64]
__device__ __align__(16) float g_Z[TOT];            // conv out (+bias), [b][o][t][v]
__device__ __align__(16) __half g_wrh[9*64*64];     // conv weights half, [k][o][c]
__device__ float g_sum1[NC], g_sq1[NC], g_sum2[NC], g_sq2[NC];
__device__ float g_s1[NC], g_t1[NC], g_s2[NC], g_t2[NC];

// ---- mma helpers ----
__device__ __forceinline__ uint32_t tf32_of(float f) {
    uint32_t u;
    asm("cvt.rna.tf32.f32 %0, %1;" : "=r"(u) : "f"(f));
    return u;
}
// pack two fp32 -> f16x2 (lo in low half): first PTX source -> UPPER half
__device__ __forceinline__ uint32_t h2pack(float lo, float hi) {
    uint32_t r;
    asm("cvt.rn.f16x2.f32 %0, %1, %2;" : "=r"(r) : "f"(hi), "f"(lo));
    return r;
}
__device__ __forceinline__ void mma_tf32(float* d,
                                         uint32_t a0, uint32_t a1, uint32_t a2, uint32_t a3,
                                         uint32_t b0, uint32_t b1) {
    asm volatile("mma.sync.aligned.m16n8k8.row.col.f32.tf32.tf32.f32 "
                 "{%0,%1,%2,%3}, {%4,%5,%6,%7}, {%8,%9}, {%0,%1,%2,%3};"
                 : "+f"(d[0]), "+f"(d[1]), "+f"(d[2]), "+f"(d[3])
                 : "r"(a0), "r"(a1), "r"(a2), "r"(a3), "r"(b0), "r"(b1));
}
__device__ __forceinline__ void mma_f16(float* d,
                                        uint32_t a0, uint32_t a1, uint32_t a2, uint32_t a3,
                                        uint32_t b0, uint32_t b1) {
    asm volatile("mma.sync.aligned.m16n8k16.row.col.f32.f16.f16.f32 "
                 "{%0,%1,%2,%3}, {%4,%5,%6,%7}, {%8,%9}, {%0,%1,%2,%3};"
                 : "+f"(d[0]), "+f"(d[1]), "+f"(d[2]), "+f"(d[3])
                 : "r"(a0), "r"(a1), "r"(a2), "r"(a3), "r"(b0), "r"(b1));
}

// ================= init: a_norm ==================
__global__ void k_init(const float* __restrict__ adj) {
    __shared__ float dinv[NV];
    int tid = threadIdx.x;
    if (tid < NV) {
        float s = 1.0f;
        for (int w = 0; w < NV; ++w) s += adj[tid*NV + w];
        dinv[tid] = rsqrtf(s);
    }
    __syncthreads();
    for (int e = tid; e < NV*NV; e += 128) {
        int v = e / NV, w = e % NV;
        float a = adj[e] + (v == w ? 1.0f : 0.0f);
        g_anorm[e] = a * dinv[v] * dinv[w];
    }
}

// ============ weight reorder + half convert: g_wrh[k][o][c]
__global__ void k_wprep(const float* __restrict__ wconv) {
    int i = blockIdx.x * 256 + threadIdx.x;
    if (i < 9*64*64) {
        int c = i & 63, ko = i >> 6;
        int o = ko & 63, k = ko >> 6;
        g_wrh[i] = __float2half(wconv[(o*64 + c)*9 + k]);
    }
}

// ============ zero BN accumulators (separate launch: positions stageB at ncu idx 5)
__global__ void k_zero() {
    int o = threadIdx.x;   // 64
    g_sum1[o] = 0.f; g_sq1[o] = 0.f; g_sum2[o] = 0.f; g_sq2[o] = 0.f;
}

// ============ stage A (mma.sync tf32): per block (b, 2 t's)  [unchanged, validated]
#define TA 2
#define A_AN 0                      // [64][68]
#define A_X  (A_AN + 64*68)         // [128][68]
#define A_W  (A_X + 128*68)         // [64][68]
#define A_T  (A_W + 64*68)          // [64][132]
#define A_SUM (A_T + 64*132)        // [64]
#define A_SQ  (A_SUM + 64)          // [64]
#define A_BM  (A_SQ + 64)           // [64]
#define A_FLOATS (A_BM + 64)
#define A_BYTES (A_FLOATS*4)

__global__ void __launch_bounds__(256, 2) k_stageA_mma(const float* __restrict__ x,
                                                       const float* __restrict__ w_mlp,
                                                       const float* __restrict__ b_mlp) {
    extern __shared__ float sa[];
    float* sAn = sa + A_AN;
    float* sX  = sa + A_X;
    float* sW  = sa + A_W;
    float* sT  = sa + A_T;
    float* ssum = sa + A_SUM;
    float* ssq  = sa + A_SQ;
    float* sbm  = sa + A_BM;

    const int tid  = threadIdx.x;
    const int wid  = tid >> 5;
    const int lane = tid & 31;
    const int gid  = lane >> 2;
    const int tid4 = lane & 3;
    const int t0 = blockIdx.x * TA;
    const int b  = blockIdx.y;

    if (tid < 64) { ssum[tid] = 0.f; ssq[tid] = 0.f; sbm[tid] = b_mlp[tid]; }
    for (int e = tid; e < 64*64; e += 256) {
        int w = e & 63, v = e >> 6;
        float val = (v < NV && w < NV) ? g_anorm[v*NV + w] : 0.f;
        sAn[v*68 + w] = __uint_as_float(tf32_of(val));
    }
    for (int e = tid; e < 128*64; e += 256) {
        int w = e & 63, n = e >> 6;
        int tl = n >> 6, c = n & 63;
        float val = (w < NV) ? x[((size_t)(b*NC + c)*NT + t0 + tl)*NV + w] : 0.f;
        sX[n*68 + w] = __uint_as_float(tf32_of(val));
    }
    for (int e = tid; e < 64*64; e += 256) {
        int c = e & 63, o = e >> 6;
        sW[o*68 + c] = __uint_as_float(tf32_of(w_mlp[o*64 + c]));
    }
    __syncthreads();

    {
        const int mtile = wid & 3;
        const int nb0 = (wid >> 2) * 8;
        float acc[8][4];
        #pragma unroll
        for (int j = 0; j < 8; ++j)
            #pragma unroll
            for (int r = 0; r < 4; ++r) acc[j][r] = 0.f;

        #pragma unroll
        for (int k8 = 0; k8 < 8; ++k8) {
            const int col = k8*8 + tid4;
            const float* ap = &sAn[(mtile*16 + gid)*68 + col];
            uint32_t a0 = __float_as_uint(ap[0]);
            uint32_t a1 = __float_as_uint(ap[8*68]);
            uint32_t a2 = __float_as_uint(ap[4]);
            uint32_t a3 = __float_as_uint(ap[8*68 + 4]);
            #pragma unroll
            for (int j = 0; j < 8; ++j) {
                const float* bp = &sX[((nb0 + j)*8 + gid)*68 + col];
                mma_tf32(acc[j], a0, a1, a2, a3,
                         __float_as_uint(bp[0]), __float_as_uint(bp[4]));
            }
        }
        #pragma unroll
        for (int j = 0; j < 8; ++j) {
            const int n = (nb0 + j)*8 + tid4*2;
            const int r = mtile*16 + gid;
            sT[r*132 + n]     = acc[j][0];
            sT[r*132 + n + 1] = acc[j][1];
            sT[(r+8)*132 + n]     = acc[j][2];
            sT[(r+8)*132 + n + 1] = acc[j][3];
        }
    }
    __syncthreads();

    {
        const int tl = wid >> 2;
        const int mtile = wid & 3;
        float acc[8][4];
        #pragma unroll
        for (int j = 0; j < 8; ++j)
            #pragma unroll
            for (int r = 0; r < 4; ++r) acc[j][r] = 0.f;

        #pragma unroll
        for (int k8 = 0; k8 < 8; ++k8) {
            const int colA = tl*64 + k8*8 + tid4;
            const float* ap = &sT[(mtile*16 + gid)*132 + colA];
            uint32_t a0 = tf32_of(ap[0]);
            uint32_t a1 = tf32_of(ap[8*132]);
            uint32_t a2 = tf32_of(ap[4]);
            uint32_t a3 = tf32_of(ap[8*132 + 4]);
            const int colB = k8*8 + tid4;
            #pragma unroll
            for (int j = 0; j < 8; ++j) {
                const float* bp = &sW[(j*8 + gid)*68 + colB];
                mma_tf32(acc[j], a0, a1, a2, a3,
                         __float_as_uint(bp[0]), __float_as_uint(bp[4]));
            }
        }

        const int t = t0 + tl;
        float* Yp = g_Ya + ((size_t)(b*NT + t) << 12);
        const int r0 = mtile*16 + gid;
        const int r1 = r0 + 8;
        const bool m1 = (r1 < NV);
        #pragma unroll
        for (int j = 0; j < 8; ++j) {
            const int o = j*8 + tid4*2;
            const float bm0 = sbm[o], bm1 = sbm[o+1];
            float y00 = acc[j][0] + bm0, y01 = acc[j][1] + bm1;
            float y10 = acc[j][2] + bm0, y11 = acc[j][3] + bm1;
            *(float2*)&Yp[r0*64 + o] = make_float2(y00, y01);
            *(float2*)&Yp[r1*64 + o] = make_float2(y10, y11);
            float s0 = y00 + (m1 ? y10 : 0.f);
            float q0 = y00*y00 + (m1 ? y10*y10 : 0.f);
            float s1 = y01 + (m1 ? y11 : 0.f);
            float q1 = y01*y01 + (m1 ? y11*y11 : 0.f);
            #pragma unroll
            for (int d = 4; d < 32; d <<= 1) {
                s0 += __shfl_xor_sync(0xFFFFFFFFu, s0, d);
                q0 += __shfl_xor_sync(0xFFFFFFFFu, q0, d);
                s1 += __shfl_xor_sync(0xFFFFFFFFu, s1, d);
                q1 += __shfl_xor_sync(0xFFFFFFFFu, q1, d);
            }
            if (lane < 4) {
                atomicAdd(&ssum[o], s0);   atomicAdd(&ssq[o], q0);
                atomicAdd(&ssum[o+1], s1); atomicAdd(&ssq[o+1], q1);
            }
        }
    }
    __syncthreads();
    if (tid < 64) {
        atomicAdd(&g_sum1[tid], ssum[tid]);
        atomicAdd(&g_sq1[tid], ssq[tid]);
    }
}

// ============ BN finalize
__global__ void k_finalize(const float* __restrict__ gamma,
                           const float* __restrict__ beta, int which) {
    int o = threadIdx.x;
    const float invN = 1.0f / (float)(NB*NT*NV);
    float sm = which ? g_sum2[o] : g_sum1[o];
    float sq = which ? g_sq2[o]  : g_sq1[o];
    float m = sm * invN;
    float var = fmaxf(sq * invN - m*m, 0.f);
    float sc = gamma[o] * rsqrtf(var + 1e-5f);
    float sh = beta[o] - m * sc;
    if (which) { g_s2[o] = sc; g_t2[o] = sh; }
    else       { g_s1[o] = sc; g_t1[o] = sh; }
}

// ============ stage B (mma.sync FP16 m16n8k16): temporal conv K=9 shifted-GEMM.
// Block = (b, 8 output t's). M=512(t,v64), N=64(o), K=576 in 4 c-chunks of 16.
// Half2 SMEM rows padded to 12 u32 -> conflict-free frags, 16B-aligned vector stores.
#define T_TILE 8
#define PADH 12
#define SA_U32 (1024*PADH)          // 12288
#define SW_U32 (576*PADH)           // 6912
#define SB_FLOATS (SA_U32 + SW_U32 + 320)
#define SB_BYTES (SB_FLOATS*4)

__global__ void __launch_bounds__(256, 1) k_stageB_mma(const float* __restrict__ bconv) {
    extern __shared__ uint32_t su[];
    uint32_t* sA32 = su;                        // [tt*64+v][12]: 8 half2 (16 c) + pad
    uint32_t* sW32 = su + SA_U32;               // [tap*64+o][12]
    float* s1v  = (float*)(su + SA_U32 + SW_U32);
    float* t1v  = s1v + 64;
    float* sbc  = t1v + 64;
    float* zsum = sbc + 64;
    float* zsq  = zsum + 64;

    const int tid  = threadIdx.x;
    const int wid  = tid >> 5;
    const int lane = tid & 31;
    const int gid  = lane >> 2;
    const int tid4 = lane & 3;
    const int t0   = blockIdx.x * T_TILE;
    const int b    = blockIdx.y;

    if (tid < 64) {
        s1v[tid] = g_s1[tid]; t1v[tid] = g_t1[tid]; sbc[tid] = bconv[tid];
        zsum[tid] = 0.f; zsq[tid] = 0.f;
    }

    float acc[4][8][4];
    #pragma unroll
    for (int mt = 0; mt < 4; ++mt)
        #pragma unroll
        for (int n8 = 0; n8 < 8; ++n8)
            #pragma unroll
            for (int r = 0; r < 4; ++r) acc[mt][n8][r] = 0.f;

    for (int ch = 0; ch < 4; ++ch) {
        const int c0 = ch * 16;
        __syncthreads();
        // ---- stage A tile: BN1 affine + ReLU + f16x2 pack; t-halo zeroed
        for (int e = tid; e < 2048; e += 256) {
            const int hh  = e & 1;           // which 8-c half of the 16-c chunk
            const int row = e >> 1;          // tt*64 + v
            const int v = row & 63, tt = row >> 6;
            const int t = t0 - 4 + tt;
            uint4 pk = make_uint4(0u, 0u, 0u, 0u);
            if (t >= 0 && t < NT) {
                const int cb = c0 + hh*8;
                const float* yp = &g_Ya[(((size_t)(b*NT + t) << 6) + v)*64 + cb];
                float4 y0 = *(const float4*)yp;
                float4 y1 = *(const float4*)(yp + 4);
                float4 sc0 = *(const float4*)&s1v[cb];
                float4 sc1 = *(const float4*)&s1v[cb + 4];
                float4 sh0 = *(const float4*)&t1v[cb];
                float4 sh1 = *(const float4*)&t1v[cb + 4];
                float z0 = fmaxf(fmaf(y0.x, sc0.x, sh0.x), 0.f);
                float z1 = fmaxf(fmaf(y0.y, sc0.y, sh0.y), 0.f);
                float z2 = fmaxf(fmaf(y0.z, sc0.z, sh0.z), 0.f);
                float z3 = fmaxf(fmaf(y0.w, sc0.w, sh0.w), 0.f);
                float z4 = fmaxf(fmaf(y1.x, sc1.x, sh1.x), 0.f);
                float z5 = fmaxf(fmaf(y1.y, sc1.y, sh1.y), 0.f);
                float z6 = fmaxf(fmaf(y1.z, sc1.z, sh1.z), 0.f);
                float z7 = fmaxf(fmaf(y1.w, sc1.w, sh1.w), 0.f);
                pk.x = h2pack(z0, z1);
                pk.y = h2pack(z2, z3);
                pk.z = h2pack(z4, z5);
                pk.w = h2pack(z6, z7);
            }
            *(uint4*)&sA32[row*PADH + hh*4] = pk;
        }
        // ---- stage W tile: straight uint4 copies of pre-halved weights
        for (int e = tid; e < 1152; e += 256) {
            const int idx = e & 1;
            const int r   = e >> 1;          // tap*64 + o
            uint4 w = ((const uint4*)g_wrh)[r*8 + ch*2 + idx];
            *(uint4*)&sW32[r*PADH + idx*4] = w;
        }
        __syncthreads();

        // ---- compute: 9 taps x (4 m16 x 8 n8) k16 mma
        for (int tap = 0; tap < 9; ++tap) {
            const int arow_base = (wid + tap)*64;
            uint32_t bf[8][2];
            #pragma unroll
            for (int n8 = 0; n8 < 8; ++n8) {
                const uint32_t* wp = &sW32[(tap*64 + n8*8 + gid)*PADH + tid4];
                bf[n8][0] = wp[0];
                bf[n8][1] = wp[4];
            }
            #pragma unroll
            for (int mt = 0; mt < 4; ++mt) {
                const uint32_t* ap = &sA32[(arow_base + mt*16 + gid)*PADH + tid4];
                uint32_t a0 = ap[0];
                uint32_t a1 = ap[8*PADH];
                uint32_t a2 = ap[4];
                uint32_t a3 = ap[8*PADH + 4];
                #pragma unroll
                for (int n8 = 0; n8 < 8; ++n8)
                    mma_f16(acc[mt][n8], a0, a1, a2, a3, bf[n8][0], bf[n8][1]);
            }
        }
    }

    // ---- epilogue: Z store (+bias) AND BN2 partial stats
    const int t = t0 + wid;
    #pragma unroll
    for (int n8 = 0; n8 < 8; ++n8) {
        const int o = n8*8 + tid4*2;
        const float b0 = sbc[o], b1 = sbc[o+1];
        const size_t base0 = ((size_t)(b*NC + o)*NT + t)*NV;
        const size_t base1 = base0 + (size_t)NT*NV;
        float s0 = 0.f, q0 = 0.f, s1 = 0.f, q1 = 0.f;
        #pragma unroll
        for (int mt = 0; mt < 4; ++mt) {
            const int v0 = mt*16 + gid;      // <= 55, always < NV
            const int v1 = v0 + 8;
            float z00 = acc[mt][n8][0] + b0, z01 = acc[mt][n8][1] + b1;
            g_Z[base0 + v0] = z00;
            g_Z[base1 + v0] = z01;
            s0 += z00; q0 += z00*z00; s1 += z01; q1 += z01*z01;
            if (v1 < NV) {
                float z10 = acc[mt][n8][2] + b0, z11 = acc[mt][n8][3] + b1;
                g_Z[base0 + v1] = z10;
                g_Z[base1 + v1] = z11;
                s0 += z10; q0 += z10*z10; s1 += z11; q1 += z11*z11;
            }
        }
        #pragma unroll
        for (int d = 4; d < 32; d <<= 1) {
            s0 += __shfl_xor_sync(0xFFFFFFFFu, s0, d);
            q0 += __shfl_xor_sync(0xFFFFFFFFu, q0, d);
            s1 += __shfl_xor_sync(0xFFFFFFFFu, s1, d);
            q1 += __shfl_xor_sync(0xFFFFFFFFu, q1, d);
        }
        if (lane < 4) {
            atomicAdd(&zsum[o], s0);   atomicAdd(&zsq[o], q0);
            atomicAdd(&zsum[o+1], s1); atomicAdd(&zsq[o+1], q1);
        }
    }
    __syncthreads();
    if (tid < 64) {
        atomicAdd(&g_sum2[tid], zsum[tid]);
        atomicAdd(&g_sq2[tid], zsq[tid]);
    }
}

// ============ stage C: out = relu(BN2(Z) + x)
__global__ void k_stageC(const float* __restrict__ x, float* __restrict__ out) {
    int i = (blockIdx.x * 256 + threadIdx.x) * 4;
    if (i >= TOT) return;
    int o = (i / NTV) & 63;
    float s = g_s2[o], tt = g_t2[o];
    float4 z  = *(const float4*)&g_Z[i];
    float4 xv = *(const float4*)&x[i];
    float4 r;
    r.x = fmaxf(fmaf(z.x, s, tt) + xv.x, 0.f);
    r.y = fmaxf(fmaf(z.y, s, tt) + xv.y, 0.f);
    r.z = fmaxf(fmaf(z.z, s, tt) + xv.z, 0.f);
    r.w = fmaxf(fmaf(z.w, s, tt) + xv.w, 0.f);
    *(float4*)&out[i] = r;
}

extern "C" void kernel_launch(void* const* d_in, const int* in_sizes, int n_in,
                              void* d_out, int out_size) {
    const float* x      = (const float*)d_in[0];
    const float* adj    = (const float*)d_in[1];
    const float* w_mlp  = (const float*)d_in[2];
    const float* b_mlp  = (const float*)d_in[3];
    const float* g1     = (const float*)d_in[4];
    const float* b1     = (const float*)d_in[5];
    const float* w_conv = (const float*)d_in[6];
    const float* b_conv = (const float*)d_in[7];
    const float* g2     = (const float*)d_in[8];
    const float* b2     = (const float*)d_in[9];
    float* out = (float*)d_out;

    cudaFuncSetAttribute(k_stageA_mma, cudaFuncAttributeMaxDynamicSharedMemorySize, A_BYTES);
    cudaFuncSetAttribute(k_stageB_mma, cudaFuncAttributeMaxDynamicSharedMemorySize, SB_BYTES);

    k_init<<<1, 128>>>(adj);                                  // launch 0
    k_wprep<<<144, 256>>>(w_conv);                            // launch 1
    k_zero<<<1, 64>>>();                                      // launch 2
    k_stageA_mma<<<dim3(NT/TA, NB), 256, A_BYTES>>>(x, w_mlp, b_mlp);  // launch 3
    k_finalize<<<1, 64>>>(g1, b1, 0);                         // launch 4
    k_stageB_mma<<<dim3(NT/T_TILE, NB), 256, SB_BYTES>>>(b_conv);      // launch 5 (ncu -s 5)
    k_finalize<<<1, 64>>>(g2, b2, 1);                         // launch 6
    k_stageC<<<TOT/4/256, 256>>>(x, out);                     // launch 7
}

// round 10
// speedup vs baseline: 3.6923x; 1.3142x over previous
#include <cuda_runtime.h>
#include <cuda_fp16.h>
#include <cstdint>

#define NB 32
#define NC 64
#define NT 256
#define NV 62
#define NTV (NT*NV)          // 15872
#define TOT (NB*NC*NT*NV)    // 32505856

// ---- device-global scratch ----
__device__ float g_anorm[NV*NV];
__device__ __align__(16) float g_Ya[NB*NT*64*64];   // padded+transposed: [b][t][v64][c64]
__device__ __align__(16) float g_Z[TOT];            // conv out (+bias), [b][o][t][v]
__device__ __align__(16) __half g_wrh[9*64*64];     // conv weights half, [k][o][c]
__device__ __align__(16) uint32_t g_anh[64*32];     // a_norm half2 [v][w/2], padded
__device__ __align__(16) uint32_t g_wmh[64*32];     // w_mlp half2 [o][c/2]
__device__ float g_sum1[NC], g_sq1[NC], g_sum2[NC], g_sq2[NC];
__device__ float g_s1[NC], g_t1[NC], g_s2[NC], g_t2[NC];

// pack two fp32 -> f16x2 (lo in low half): first PTX source -> UPPER half
__device__ __forceinline__ uint32_t h2pack(float lo, float hi) {
    uint32_t r;
    asm("cvt.rn.f16x2.f32 %0, %1, %2;" : "=r"(r) : "f"(hi), "f"(lo));
    return r;
}
__device__ __forceinline__ void mma_f16(float* d,
                                        uint32_t a0, uint32_t a1, uint32_t a2, uint32_t a3,
                                        uint32_t b0, uint32_t b1) {
    asm volatile("mma.sync.aligned.m16n8k16.row.col.f32.f16.f16.f32 "
                 "{%0,%1,%2,%3}, {%4,%5,%6,%7}, {%8,%9}, {%0,%1,%2,%3};"
                 : "+f"(d[0]), "+f"(d[1]), "+f"(d[2]), "+f"(d[3])
                 : "r"(a0), "r"(a1), "r"(a2), "r"(a3), "r"(b0), "r"(b1));
}

// ================= init: a_norm ==================
__global__ void k_init(const float* __restrict__ adj) {
    __shared__ float dinv[NV];
    int tid = threadIdx.x;
    if (tid < NV) {
        float s = 1.0f;
        for (int w = 0; w < NV; ++w) s += adj[tid*NV + w];
        dinv[tid] = rsqrtf(s);
    }
    __syncthreads();
    for (int e = tid; e < NV*NV; e += 128) {
        int v = e / NV, w = e % NV;
        float a = adj[e] + (v == w ? 1.0f : 0.0f);
        g_anorm[e] = a * dinv[v] * dinv[w];
    }
}

// ============ prep: conv weights [k][o][c] half; a_norm + w_mlp half2 packs
__global__ void k_wprep(const float* __restrict__ wconv,
                        const float* __restrict__ w_mlp) {
    int i = blockIdx.x * 256 + threadIdx.x;     // 160*256 = 40960
    if (i < 36864) {
        int c = i & 63, ko = i >> 6;
        int o = ko & 63, k = ko >> 6;
        g_wrh[i] = __float2half(wconv[(o*64 + c)*9 + k]);
    } else if (i < 36864 + 2048) {
        int j = i - 36864;
        int v = j >> 5, w2 = j & 31;
        int w = w2 * 2;
        float lo = (v < NV && w < NV)     ? g_anorm[v*NV + w]     : 0.f;
        float hi = (v < NV && w+1 < NV)   ? g_anorm[v*NV + w + 1] : 0.f;
        g_anh[j] = h2pack(lo, hi);
    } else if (i < 36864 + 4096) {
        int j = i - 36864 - 2048;
        int o = j >> 5, c2 = j & 31;
        g_wmh[j] = h2pack(w_mlp[o*64 + c2*2], w_mlp[o*64 + c2*2 + 1]);
    }
}

// ============ zero BN accumulators
__global__ void k_zero() {
    int o = threadIdx.x;   // 64
    g_sum1[o] = 0.f; g_sq1[o] = 0.f; g_sum2[o] = 0.f; g_sq2[o] = 0.f;
}

// ============ stage A (mma.sync fp16 k16): per block (b, 4 t's)
// GEMM1: T1[v][n=(tl,c)] = An[v][w] * X[n][w]^T   (M=64, N=256, K=64)
// GEMM2 per tl: Y[v][o]  = T1[v][c] * Wm[o][c]^T  (M=64, N=64, K=64)
// SMEM rows in u32(half2): stride 36 / 132 -> conflict-free fragments.
#define TA 4
#define AX_U 0                     // sX  [256][36]
#define AN_U (AX_U + 256*36)       // sAn [64][36]
#define AW_U (AN_U + 64*36)        // sWm [64][36]
#define AT_U (AW_U + 64*36)        // sT1 [64][132]
#define AS_U (AT_U + 64*132)       // ssum[64], ssq[64], sbm[64]
#define A_U32 (AS_U + 192)
#define A_BYTES (A_U32*4)

__global__ void __launch_bounds__(256, 2) k_stageA_mma(const float* __restrict__ x,
                                                       const float* __restrict__ b_mlp) {
    extern __shared__ uint32_t su[];
    uint32_t* sX  = su + AX_U;
    uint32_t* sAn = su + AN_U;
    uint32_t* sWm = su + AW_U;
    uint32_t* sT1 = su + AT_U;
    float* ssum = (float*)(su + AS_U);
    float* ssq  = ssum + 64;
    float* sbm  = ssq + 64;

    const int tid  = threadIdx.x;
    const int wid  = tid >> 5;
    const int lane = tid & 31;
    const int gid  = lane >> 2;
    const int tid4 = lane & 3;
    const int t0 = blockIdx.x * TA;
    const int b  = blockIdx.y;

    if (tid < 64) { ssum[tid] = 0.f; ssq[tid] = 0.f; sbm[tid] = b_mlp[tid]; }
    // constants: straight uint4 copies of pre-halved An / Wm (8 uint4 per 36-u32 row)
    for (int e = tid; e < 512; e += 256) {
        int r = e >> 3, q = e & 7;
        *(uint4*)&sAn[r*36 + q*4] = ((const uint4*)g_anh)[e];
        *(uint4*)&sWm[r*36 + q*4] = ((const uint4*)g_wmh)[e];
    }
    // X: rows n = tl*64+c, 32 half2 of w (pad w>=62 zero)
    for (int e = tid; e < 8192; e += 256) {
        int w2 = e & 31, n = e >> 5;
        int tl = n >> 6, c = n & 63;
        int w = w2 * 2;
        uint32_t pk = 0u;
        if (w < NV) {
            const float* xp = &x[((size_t)(b*NC + c)*NT + t0 + tl)*NV + w];
            if (w + 1 < NV) { float2 f = *(const float2*)xp; pk = h2pack(f.x, f.y); }
            else            { pk = h2pack(xp[0], 0.f); }
        }
        sX[n*36 + w2] = pk;
    }
    __syncthreads();

    // ---- GEMM1: warp: mtile = wid&3 (v), n8 range = (wid>>2)*16 .. +16
    {
        const int mtile = wid & 3;
        const int nb0 = (wid >> 2) * 16;
        float acc[16][4];
        #pragma unroll
        for (int j = 0; j < 16; ++j)
            #pragma unroll
            for (int r = 0; r < 4; ++r) acc[j][r] = 0.f;

        #pragma unroll
        for (int k16 = 0; k16 < 4; ++k16) {
            const int col = k16*8 + tid4;
            const uint32_t* ap = &sAn[(mtile*16 + gid)*36 + col];
            uint32_t a0 = ap[0], a1 = ap[8*36], a2 = ap[4], a3 = ap[8*36 + 4];
            #pragma unroll
            for (int j = 0; j < 16; ++j) {
                const uint32_t* bp = &sX[((nb0 + j)*8 + gid)*36 + col];
                mma_f16(acc[j], a0, a1, a2, a3, bp[0], bp[4]);
            }
        }
        // write T1 as half2: rows v, u32 col = n8*4 + tid4
        #pragma unroll
        for (int j = 0; j < 16; ++j) {
            const int nc = (nb0 + j)*4 + tid4;
            const int r = mtile*16 + gid;
            sT1[r*132 + nc]     = h2pack(acc[j][0], acc[j][1]);
            sT1[(r+8)*132 + nc] = h2pack(acc[j][2], acc[j][3]);
        }
    }
    __syncthreads();

    // ---- GEMM2: warp: tl = wid>>1, mtiles {m0, m0+1} with m0 = (wid&1)*2
    {
        const int tl = wid >> 1;
        const int m0 = (wid & 1) * 2;
        float acc[2][8][4];
        #pragma unroll
        for (int mt = 0; mt < 2; ++mt)
            #pragma unroll
            for (int j = 0; j < 8; ++j)
                #pragma unroll
                for (int r = 0; r < 4; ++r) acc[mt][j][r] = 0.f;

        #pragma unroll
        for (int k16 = 0; k16 < 4; ++k16) {
            const int colA = tl*32 + k16*8 + tid4;
            const int colB = k16*8 + tid4;
            uint32_t af[2][4];
            #pragma unroll
            for (int mt = 0; mt < 2; ++mt) {
                const uint32_t* ap = &sT1[((m0+mt)*16 + gid)*132 + colA];
                af[mt][0] = ap[0]; af[mt][1] = ap[8*132];
                af[mt][2] = ap[4]; af[mt][3] = ap[8*132 + 4];
            }
            #pragma unroll
            for (int j = 0; j < 8; ++j) {
                const uint32_t* bp = &sWm[(j*8 + gid)*36 + colB];
                uint32_t b0 = bp[0], b1 = bp[4];
                mma_f16(acc[0][j], af[0][0], af[0][1], af[0][2], af[0][3], b0, b1);
                mma_f16(acc[1][j], af[1][0], af[1][1], af[1][2], af[1][3], b0, b1);
            }
        }

        // ---- epilogue: bias, store Ya[b][t][v][o] fp32, BN1 stats (v<62)
        const int t = t0 + tl;
        float* Yp = g_Ya + ((size_t)(b*NT + t) << 12);
        #pragma unroll
        for (int j = 0; j < 8; ++j) {
            const int o = j*8 + tid4*2;
            const float bm0 = sbm[o], bm1 = sbm[o+1];
            float s0 = 0.f, q0 = 0.f, s1 = 0.f, q1 = 0.f;
            #pragma unroll
            for (int mt = 0; mt < 2; ++mt) {
                const int r0 = (m0+mt)*16 + gid;     // <= 55
                const int r1 = r0 + 8;               // may be 62/63 -> mask stats
                const bool m1 = (r1 < NV);
                float y00 = acc[mt][j][0] + bm0, y01 = acc[mt][j][1] + bm1;
                float y10 = acc[mt][j][2] + bm0, y11 = acc[mt][j][3] + bm1;
                *(float2*)&Yp[r0*64 + o] = make_float2(y00, y01);
                *(float2*)&Yp[r1*64 + o] = make_float2(y10, y11);
                s0 += y00 + (m1 ? y10 : 0.f);
                q0 += y00*y00 + (m1 ? y10*y10 : 0.f);
                s1 += y01 + (m1 ? y11 : 0.f);
                q1 += y01*y01 + (m1 ? y11*y11 : 0.f);
            }
            #pragma unroll
            for (int d = 4; d < 32; d <<= 1) {
                s0 += __shfl_xor_sync(0xFFFFFFFFu, s0, d);
                q0 += __shfl_xor_sync(0xFFFFFFFFu, q0, d);
                s1 += __shfl_xor_sync(0xFFFFFFFFu, s1, d);
                q1 += __shfl_xor_sync(0xFFFFFFFFu, q1, d);
            }
            if (lane < 4) {
                atomicAdd(&ssum[o], s0);   atomicAdd(&ssq[o], q0);
                atomicAdd(&ssum[o+1], s1); atomicAdd(&ssq[o+1], q1);
            }
        }
    }
    __syncthreads();
    if (tid < 64) {
        atomicAdd(&g_sum1[tid], ssum[tid]);
        atomicAdd(&g_sq1[tid], ssq[tid]);
    }
}

// ============ BN finalize
__global__ void k_finalize(const float* __restrict__ gamma,
                           const float* __restrict__ beta, int which) {
    int o = threadIdx.x;
    const float invN = 1.0f / (float)(NB*NT*NV);
    float sm = which ? g_sum2[o] : g_sum1[o];
    float sq = which ? g_sq2[o]  : g_sq1[o];
    float m = sm * invN;
    float var = fmaxf(sq * invN - m*m, 0.f);
    float sc = gamma[o] * rsqrtf(var + 1e-5f);
    float sh = beta[o] - m * sc;
    if (which) { g_s2[o] = sc; g_t2[o] = sh; }
    else       { g_s1[o] = sc; g_t1[o] = sh; }
}

// ============ stage B (mma.sync FP16 m16n8k16)  [unchanged, validated]
#define T_TILE 8
#define PADH 12
#define SA_U32 (1024*PADH)          // 12288
#define SW_U32 (576*PADH)           // 6912
#define SB_FLOATS (SA_U32 + SW_U32 + 320)
#define SB_BYTES (SB_FLOATS*4)

__global__ void __launch_bounds__(256, 1) k_stageB_mma(const float* __restrict__ bconv) {
    extern __shared__ uint32_t su[];
    uint32_t* sA32 = su;
    uint32_t* sW32 = su + SA_U32;
    float* s1v  = (float*)(su + SA_U32 + SW_U32);
    float* t1v  = s1v + 64;
    float* sbc  = t1v + 64;
    float* zsum = sbc + 64;
    float* zsq  = zsum + 64;

    const int tid  = threadIdx.x;
    const int wid  = tid >> 5;
    const int lane = tid & 31;
    const int gid  = lane >> 2;
    const int tid4 = lane & 3;
    const int t0   = blockIdx.x * T_TILE;
    const int b    = blockIdx.y;

    if (tid < 64) {
        s1v[tid] = g_s1[tid]; t1v[tid] = g_t1[tid]; sbc[tid] = bconv[tid];
        zsum[tid] = 0.f; zsq[tid] = 0.f;
    }

    float acc[4][8][4];
    #pragma unroll
    for (int mt = 0; mt < 4; ++mt)
        #pragma unroll
        for (int n8 = 0; n8 < 8; ++n8)
            #pragma unroll
            for (int r = 0; r < 4; ++r) acc[mt][n8][r] = 0.f;

    for (int ch = 0; ch < 4; ++ch) {
        const int c0 = ch * 16;
        __syncthreads();
        for (int e = tid; e < 2048; e += 256) {
            const int hh  = e & 1;
            const int row = e >> 1;
            const int v = row & 63, tt = row >> 6;
            const int t = t0 - 4 + tt;
            uint4 pk = make_uint4(0u, 0u, 0u, 0u);
            if (t >= 0 && t < NT) {
                const int cb = c0 + hh*8;
                const float* yp = &g_Ya[(((size_t)(b*NT + t) << 6) + v)*64 + cb];
                float4 y0 = *(const float4*)yp;
                float4 y1 = *(const float4*)(yp + 4);
                float4 sc0 = *(const float4*)&s1v[cb];
                float4 sc1 = *(const float4*)&s1v[cb + 4];
                float4 sh0 = *(const float4*)&t1v[cb];
                float4 sh1 = *(const float4*)&t1v[cb + 4];
                float z0 = fmaxf(fmaf(y0.x, sc0.x, sh0.x), 0.f);
                float z1 = fmaxf(fmaf(y0.y, sc0.y, sh0.y), 0.f);
                float z2 = fmaxf(fmaf(y0.z, sc0.z, sh0.z), 0.f);
                float z3 = fmaxf(fmaf(y0.w, sc0.w, sh0.w), 0.f);
                float z4 = fmaxf(fmaf(y1.x, sc1.x, sh1.x), 0.f);
                float z5 = fmaxf(fmaf(y1.y, sc1.y, sh1.y), 0.f);
                float z6 = fmaxf(fmaf(y1.z, sc1.z, sh1.z), 0.f);
                float z7 = fmaxf(fmaf(y1.w, sc1.w, sh1.w), 0.f);
                pk.x = h2pack(z0, z1);
                pk.y = h2pack(z2, z3);
                pk.z = h2pack(z4, z5);
                pk.w = h2pack(z6, z7);
            }
            *(uint4*)&sA32[row*PADH + hh*4] = pk;
        }
        for (int e = tid; e < 1152; e += 256) {
            const int idx = e & 1;
            const int r   = e >> 1;
            uint4 w = ((const uint4*)g_wrh)[r*8 + ch*2 + idx];
            *(uint4*)&sW32[r*PADH + idx*4] = w;
        }
        __syncthreads();

        for (int tap = 0; tap < 9; ++tap) {
            const int arow_base = (wid + tap)*64;
            uint32_t bf[8][2];
            #pragma unroll
            for (int n8 = 0; n8 < 8; ++n8) {
                const uint32_t* wp = &sW32[(tap*64 + n8*8 + gid)*PADH + tid4];
                bf[n8][0] = wp[0];
                bf[n8][1] = wp[4];
            }
            #pragma unroll
            for (int mt = 0; mt < 4; ++mt) {
                const uint32_t* ap = &sA32[(arow_base + mt*16 + gid)*PADH + tid4];
                uint32_t a0 = ap[0];
                uint32_t a1 = ap[8*PADH];
                uint32_t a2 = ap[4];
                uint32_t a3 = ap[8*PADH + 4];
                #pragma unroll
                for (int n8 = 0; n8 < 8; ++n8)
                    mma_f16(acc[mt][n8], a0, a1, a2, a3, bf[n8][0], bf[n8][1]);
            }
        }
    }

    const int t = t0 + wid;
    #pragma unroll
    for (int n8 = 0; n8 < 8; ++n8) {
        const int o = n8*8 + tid4*2;
        const float b0 = sbc[o], b1 = sbc[o+1];
        const size_t base0 = ((size_t)(b*NC + o)*NT + t)*NV;
        const size_t base1 = base0 + (size_t)NT*NV;
        float s0 = 0.f, q0 = 0.f, s1 = 0.f, q1 = 0.f;
        #pragma unroll
        for (int mt = 0; mt < 4; ++mt) {
            const int v0 = mt*16 + gid;
            const int v1 = v0 + 8;
            float z00 = acc[mt][n8][0] + b0, z01 = acc[mt][n8][1] + b1;
            g_Z[base0 + v0] = z00;
            g_Z[base1 + v0] = z01;
            s0 += z00; q0 += z00*z00; s1 += z01; q1 += z01*z01;
            if (v1 < NV) {
                float z10 = acc[mt][n8][2] + b0, z11 = acc[mt][n8][3] + b1;
                g_Z[base0 + v1] = z10;
                g_Z[base1 + v1] = z11;
                s0 += z10; q0 += z10*z10; s1 += z11; q1 += z11*z11;
            }
        }
        #pragma unroll
        for (int d = 4; d < 32; d <<= 1) {
            s0 += __shfl_xor_sync(0xFFFFFFFFu, s0, d);
            q0 += __shfl_xor_sync(0xFFFFFFFFu, q0, d);
            s1 += __shfl_xor_sync(0xFFFFFFFFu, s1, d);
            q1 += __shfl_xor_sync(0xFFFFFFFFu, q1, d);
        }
        if (lane < 4) {
            atomicAdd(&zsum[o], s0);   atomicAdd(&zsq[o], q0);
            atomicAdd(&zsum[o+1], s1); atomicAdd(&zsq[o+1], q1);
        }
    }
    __syncthreads();
    if (tid < 64) {
        atomicAdd(&g_sum2[tid], zsum[tid]);
        atomicAdd(&g_sq2[tid], zsq[tid]);
    }
}

// ============ stage C: out = relu(BN2(Z) + x)
__global__ void k_stageC(const float* __restrict__ x, float* __restrict__ out) {
    int i = (blockIdx.x * 256 + threadIdx.x) * 4;
    if (i >= TOT) return;
    int o = (i / NTV) & 63;
    float s = g_s2[o], tt = g_t2[o];
    float4 z  = *(const float4*)&g_Z[i];
    float4 xv = *(const float4*)&x[i];
    float4 r;
    r.x = fmaxf(fmaf(z.x, s, tt) + xv.x, 0.f);
    r.y = fmaxf(fmaf(z.y, s, tt) + xv.y, 0.f);
    r.z = fmaxf(fmaf(z.z, s, tt) + xv.z, 0.f);
    r.w = fmaxf(fmaf(z.w, s, tt) + xv.w, 0.f);
    *(float4*)&out[i] = r;
}

extern "C" void kernel_launch(void* const* d_in, const int* in_sizes, int n_in,
                              void* d_out, int out_size) {
    const float* x      = (const float*)d_in[0];
    const float* adj    = (const float*)d_in[1];
    const float* w_mlp  = (const float*)d_in[2];
    const float* b_mlp  = (const float*)d_in[3];
    const float* g1     = (const float*)d_in[4];
    const float* b1     = (const float*)d_in[5];
    const float* w_conv = (const float*)d_in[6];
    const float* b_conv = (const float*)d_in[7];
    const float* g2     = (const float*)d_in[8];
    const float* b2     = (const float*)d_in[9];
    float* out = (float*)d_out;

    cudaFuncSetAttribute(k_stageA_mma, cudaFuncAttributeMaxDynamicSharedMemorySize, A_BYTES);
    cudaFuncSetAttribute(k_stageB_mma, cudaFuncAttributeMaxDynamicSharedMemorySize, SB_BYTES);

    k_init<<<1, 128>>>(adj);
    k_wprep<<<160, 256>>>(w_conv, w_mlp);
    k_zero<<<1, 64>>>();
    k_stageA_mma<<<dim3(NT/TA, NB), 256, A_BYTES>>>(x, b_mlp);
    k_finalize<<<1, 64>>>(g1, b1, 0);
    k_stageB_mma<<<dim3(NT/T_TILE, NB), 256, SB_BYTES>>>(b_conv);
    k_finalize<<<1, 64>>>(g2, b2, 1);
    k_stageC<<<TOT/4/256, 256>>>(x, out);
}